// round 5
// baseline (speedup 1.0000x reference)
#include <cuda_runtime.h>
#include <cuda_bf16.h>
#include <cstdint>

// Problem constants
#define BB 8
#define LQ 2048
#define LK 2048
#define DW 1024
#define DKD 128
#define INV_TEMP 0.08838834764831845f   // 1/sqrt(128)

// Projected q/k/v scratch (tf32-rounded values stored as fp32)
__device__ float g_qs[BB * LQ * DKD];
__device__ float g_ks[BB * LK * DKD];
__device__ float g_vs[BB * LK * DKD];

// ---------------------------------------------------------------------------
// helpers
// ---------------------------------------------------------------------------
__device__ __forceinline__ float to_tf32(float x) {
    uint32_t u;
    asm("cvt.rna.tf32.f32 %0, %1;" : "=r"(u) : "f"(x));
    return __uint_as_float(u);
}
__device__ __forceinline__ uint32_t tf32_bits(float x) {
    uint32_t u;
    asm("cvt.rna.tf32.f32 %0, %1;" : "=r"(u) : "f"(x));
    return u;
}
__device__ __forceinline__ uint32_t fbits(float x) { return __float_as_uint(x); }

// mma.sync m16n8k8 tf32: D = A*B + D (A row-major, B col-major)
__device__ __forceinline__ void mma_tf32(float& c0, float& c1, float& c2, float& c3,
                                         uint32_t a0, uint32_t a1, uint32_t a2, uint32_t a3,
                                         uint32_t b0, uint32_t b1) {
    asm volatile(
        "mma.sync.aligned.m16n8k8.row.col.f32.tf32.tf32.f32 "
        "{%0,%1,%2,%3}, {%4,%5,%6,%7}, {%8,%9}, {%0,%1,%2,%3};"
        : "+f"(c0), "+f"(c1), "+f"(c2), "+f"(c3)
        : "r"(a0), "r"(a1), "r"(a2), "r"(a3), "r"(b0), "r"(b1));
}

__device__ __forceinline__ void cp16(uint32_t saddr, const void* gaddr) {
    asm volatile("cp.async.ca.shared.global [%0], [%1], 16;" :: "r"(saddr), "l"(gaddr));
}

// ---------------------------------------------------------------------------
// Projection GEMM via tf32 MMA + cp.async double buffering.
// C[16384,128] = A[16384,1024] * W[1024,128]; outputs tf32-ROUNDED so the
// attention kernel never needs cvt in its hot loop.
// ---------------------------------------------------------------------------
#define PJ_AS0 0
#define PJ_AS1 (PJ_AS0 + 128 * 36)
#define PJ_WS0 (PJ_AS1 + 128 * 36)
#define PJ_WS1 (PJ_WS0 + 32 * 132)
#define PJ_SMF (PJ_WS1 + 32 * 132)
#define PJ_SMB (PJ_SMF * 4)

__global__ __launch_bounds__(256) void proj_mma(
    const float* __restrict__ q, const float* __restrict__ k,
    const float* __restrict__ v, const float* __restrict__ Wq,
    const float* __restrict__ Wk, const float* __restrict__ Wv)
{
    const float* A; const float* W; float* C;
    if (blockIdx.z == 0)      { A = q; W = Wq; C = g_qs; }
    else if (blockIdx.z == 1) { A = k; W = Wk; C = g_ks; }
    else                      { A = v; W = Wv; C = g_vs; }

    extern __shared__ float psm[];
    const uint32_t sbase = (uint32_t)__cvta_generic_to_shared(psm);

    const int tid  = threadIdx.x;
    const int lane = tid & 31;
    const int warp = tid >> 5;
    const int g    = lane >> 2;
    const int tig  = lane & 3;
    const int m0   = (warp & 3) * 32;
    const int n0   = (warp >> 2) * 64;
    const int row0 = blockIdx.x * 128;

    float acc[2][8][4];
#pragma unroll
    for (int mt = 0; mt < 2; mt++)
#pragma unroll
        for (int nt = 0; nt < 8; nt++)
#pragma unroll
            for (int c = 0; c < 4; c++) acc[mt][nt][c] = 0.0f;

    auto issue_tiles = [&](int buf, int k0) {
        const int aoff = buf ? PJ_AS1 : PJ_AS0;
        const int woff = buf ? PJ_WS1 : PJ_WS0;
#pragma unroll
        for (int it = 0; it < 4; it++) {
            int f4 = tid + it * 256;
            int r  = f4 >> 3, c4 = f4 & 7;
            cp16(sbase + (uint32_t)(aoff + r * 36 + c4 * 4) * 4,
                 &A[(size_t)(row0 + r) * DW + k0 + c4 * 4]);
        }
#pragma unroll
        for (int it = 0; it < 4; it++) {
            int f4 = tid + it * 256;
            int r  = f4 >> 5, c4 = f4 & 31;
            cp16(sbase + (uint32_t)(woff + r * 132 + c4 * 4) * 4,
                 &W[(size_t)(k0 + r) * DKD + c4 * 4]);
        }
    };

    issue_tiles(0, 0);
    asm volatile("cp.async.commit_group;");

    for (int i = 0; i < 32; i++) {
        const int buf = i & 1;
        if (i + 1 < 32) {
            issue_tiles(1 - buf, (i + 1) * 32);
            asm volatile("cp.async.commit_group;");
            asm volatile("cp.async.wait_group 1;");
        } else {
            asm volatile("cp.async.wait_group 0;");
        }
        __syncthreads();

        const float* As = psm + (buf ? PJ_AS1 : PJ_AS0);
        const float* Ws = psm + (buf ? PJ_WS1 : PJ_WS0);

#pragma unroll
        for (int kk = 0; kk < 32; kk += 8) {
            uint32_t a[2][4];
#pragma unroll
            for (int mt = 0; mt < 2; mt++) {
                int mr = m0 + mt * 16;
                a[mt][0] = tf32_bits(As[(mr + g) * 36 + kk + tig]);
                a[mt][1] = tf32_bits(As[(mr + g + 8) * 36 + kk + tig]);
                a[mt][2] = tf32_bits(As[(mr + g) * 36 + kk + tig + 4]);
                a[mt][3] = tf32_bits(As[(mr + g + 8) * 36 + kk + tig + 4]);
            }
#pragma unroll
            for (int nt = 0; nt < 8; nt++) {
                uint32_t b0 = tf32_bits(Ws[(kk + tig) * 132 + n0 + nt * 8 + g]);
                uint32_t b1 = tf32_bits(Ws[(kk + tig + 4) * 132 + n0 + nt * 8 + g]);
#pragma unroll
                for (int mt = 0; mt < 2; mt++)
                    mma_tf32(acc[mt][nt][0], acc[mt][nt][1], acc[mt][nt][2], acc[mt][nt][3],
                             a[mt][0], a[mt][1], a[mt][2], a[mt][3], b0, b1);
            }
        }
        __syncthreads();
    }

    // Epilogue — tf32-round the outputs
#pragma unroll
    for (int mt = 0; mt < 2; mt++) {
        int r0 = row0 + m0 + mt * 16 + g;
#pragma unroll
        for (int nt = 0; nt < 8; nt++) {
            int col = n0 + nt * 8 + tig * 2;
            float2 o0 = make_float2(to_tf32(acc[mt][nt][0]), to_tf32(acc[mt][nt][1]));
            float2 o1 = make_float2(to_tf32(acc[mt][nt][2]), to_tf32(acc[mt][nt][3]));
            *(float2*)&C[(size_t)r0 * DKD + col]       = o0;
            *(float2*)&C[(size_t)(r0 + 8) * DKD + col] = o1;
        }
    }
}

// ---------------------------------------------------------------------------
// Fused flash attention, register-resident softmax, split-kv warps.
// CTA: 128 q-rows, 512 threads = 16 warps.
//   warp w: q-group = w&7 (16 rows), kv-half = w>>3 (32 of the 64 kv cols).
// Per K-block(64): S 16x32 in regs -> in-register softmax (quad shuffles) ->
// P transposed to A-fragments via quad shuffles -> PV 16x128 accumulate.
// cp.async double-buffered K/V; 2 barriers per block. Split-kv merge at end.
// ---------------------------------------------------------------------------
#define QST 132
#define AT_Q  0
#define AT_K0 (128 * 132)            // 16896
#define AT_K1 (AT_K0 + 64 * 132)     // 25344
#define AT_V0 (AT_K1 + 64 * 132)     // 33792
#define AT_V1 (AT_V0 + 64 * 136)     // 42496
#define AT_SMF (AT_V1 + 64 * 136)    // 51200 floats
#define AT_SMB (AT_SMF * 4)          // 204800 bytes
// merge scratch overlays K0/K1 region (16384 + 256 <= 16896)
#define MG_O  AT_K0
#define MG_ML (AT_K0 + 16384)

__global__ __launch_bounds__(512) void attn_mma(
    const int* __restrict__ memory_lengths, float* __restrict__ out)
{
    extern __shared__ float sm[];
    const uint32_t sb = (uint32_t)__cvta_generic_to_shared(sm);

    const int tid  = threadIdx.x;
    const int lane = tid & 31;
    const int warp = tid >> 5;
    const int g    = lane >> 2;
    const int tig  = lane & 3;
    const int group = warp & 7;      // q-row group
    const int half  = warp >> 3;     // kv half
    const int b    = blockIdx.y;
    const int q0   = blockIdx.x * 128;
    const int memlen = memory_lengths[b];
    const int r0   = group * 16;
    const int kvh  = half * 32;

    const float* Q = g_qs + (size_t)b * LQ * DKD;
    const float* K = g_ks + (size_t)b * LK * DKD;
    const float* V = g_vs + (size_t)b * LK * DKD;

    // Async Q load (128x128 -> 4096 f4 / 512 thr = 8 each)
#pragma unroll
    for (int it = 0; it < 8; it++) {
        int f4 = tid + it * 512;
        int qr = f4 >> 5, qc4 = f4 & 31;
        cp16(sb + (uint32_t)(AT_Q + qr * QST + qc4 * 4) * 4,
             &Q[(size_t)(q0 + qr) * DKD + qc4 * 4]);
    }

    auto issue_kv = [&](int bufsel, int kv0) {
        const int kof = bufsel ? AT_K1 : AT_K0;
        const int vof = bufsel ? AT_V1 : AT_V0;
#pragma unroll
        for (int it = 0; it < 4; it++) {
            int f4 = tid + it * 512;
            int kr = f4 >> 5, kc4 = f4 & 31;
            cp16(sb + (uint32_t)(kof + kr * 132 + kc4 * 4) * 4,
                 &K[(size_t)(kv0 + kr) * DKD + kc4 * 4]);
            cp16(sb + (uint32_t)(vof + kr * 136 + kc4 * 4) * 4,
                 &V[(size_t)(kv0 + kr) * DKD + kc4 * 4]);
        }
    };

    issue_kv(0, 0);
    asm volatile("cp.async.commit_group;");

    float oacc[16][4];
#pragma unroll
    for (int dt = 0; dt < 16; dt++)
#pragma unroll
        for (int c = 0; c < 4; c++) oacc[dt][c] = 0.0f;
    float m0r = -1e30f, m1r = -1e30f, l0r = 0.0f, l1r = 0.0f;

    const int nkb = (memlen + 63) >> 6;
    const float* Qs = sm + AT_Q;

    for (int kb = 0; kb < nkb; kb++) {
        const int buf = kb & 1;
        __syncthreads();                 // everyone done reading buf^1
        if (kb + 1 < nkb) {
            issue_kv(buf ^ 1, (kb + 1) * 64);
            asm volatile("cp.async.commit_group;");
            asm volatile("cp.async.wait_group 1;");
        } else {
            asm volatile("cp.async.wait_group 0;");
        }
        __syncthreads();                 // block kb visible CTA-wide

        const float* Ks = sm + (buf ? AT_K1 : AT_K0);
        const float* Vs = sm + (buf ? AT_V1 : AT_V0);

        // ---- S = Q K^T : warp tile 16(q) x 32(kv) ----
        float sacc[4][4];
#pragma unroll
        for (int nt = 0; nt < 4; nt++)
#pragma unroll
            for (int c = 0; c < 4; c++) sacc[nt][c] = 0.0f;

#pragma unroll
        for (int kk = 0; kk < 128; kk += 8) {
            uint32_t a0 = fbits(Qs[(r0 + g) * QST + kk + tig]);
            uint32_t a1 = fbits(Qs[(r0 + g + 8) * QST + kk + tig]);
            uint32_t a2 = fbits(Qs[(r0 + g) * QST + kk + tig + 4]);
            uint32_t a3 = fbits(Qs[(r0 + g + 8) * QST + kk + tig + 4]);
#pragma unroll
            for (int nt = 0; nt < 4; nt++) {
                uint32_t b0 = fbits(Ks[(kvh + nt * 8 + g) * 132 + kk + tig]);
                uint32_t b1 = fbits(Ks[(kvh + nt * 8 + g) * 132 + kk + tig + 4]);
                mma_tf32(sacc[nt][0], sacc[nt][1], sacc[nt][2], sacc[nt][3],
                         a0, a1, a2, a3, b0, b1);
            }
        }

        // ---- mask + scale + in-register online softmax ----
        const int cbase = kb * 64 + kvh + tig * 2;
        float mx0 = -1e30f, mx1 = -1e30f;
#pragma unroll
        for (int nt = 0; nt < 4; nt++) {
            int c0 = cbase + nt * 8;
            bool v0 = c0 < memlen, v1 = (c0 + 1) < memlen;
            sacc[nt][0] = v0 ? sacc[nt][0] * INV_TEMP : -1e30f;
            sacc[nt][1] = v1 ? sacc[nt][1] * INV_TEMP : -1e30f;
            sacc[nt][2] = v0 ? sacc[nt][2] * INV_TEMP : -1e30f;
            sacc[nt][3] = v1 ? sacc[nt][3] * INV_TEMP : -1e30f;
            mx0 = fmaxf(mx0, fmaxf(sacc[nt][0], sacc[nt][1]));
            mx1 = fmaxf(mx1, fmaxf(sacc[nt][2], sacc[nt][3]));
        }
        mx0 = fmaxf(mx0, __shfl_xor_sync(0xffffffff, mx0, 1));
        mx0 = fmaxf(mx0, __shfl_xor_sync(0xffffffff, mx0, 2));
        mx1 = fmaxf(mx1, __shfl_xor_sync(0xffffffff, mx1, 1));
        mx1 = fmaxf(mx1, __shfl_xor_sync(0xffffffff, mx1, 2));

        float mn0 = fmaxf(m0r, mx0), mn1 = fmaxf(m1r, mx1);
        float sc0 = __expf(m0r - mn0), sc1 = __expf(m1r - mn1);
        float s0 = 0.0f, s1 = 0.0f;
#pragma unroll
        for (int nt = 0; nt < 4; nt++) {
            float p;
            p = __expf(sacc[nt][0] - mn0); s0 += p; sacc[nt][0] = to_tf32(p);
            p = __expf(sacc[nt][1] - mn0); s0 += p; sacc[nt][1] = to_tf32(p);
            p = __expf(sacc[nt][2] - mn1); s1 += p; sacc[nt][2] = to_tf32(p);
            p = __expf(sacc[nt][3] - mn1); s1 += p; sacc[nt][3] = to_tf32(p);
        }
        s0 += __shfl_xor_sync(0xffffffff, s0, 1);
        s0 += __shfl_xor_sync(0xffffffff, s0, 2);
        s1 += __shfl_xor_sync(0xffffffff, s1, 1);
        s1 += __shfl_xor_sync(0xffffffff, s1, 2);
        l0r = l0r * sc0 + s0;  l1r = l1r * sc1 + s1;
        m0r = mn0;  m1r = mn1;

        // ---- rescale O, then O += P @ V (16 x 128) ----
#pragma unroll
        for (int dt = 0; dt < 16; dt++) {
            oacc[dt][0] *= sc0; oacc[dt][1] *= sc0;
            oacc[dt][2] *= sc1; oacc[dt][3] *= sc1;
        }

        const int srcA = (lane & ~3) | (tig >> 1);
        const int srcB = srcA + 2;
        const bool odd = (tig & 1);
#pragma unroll
        for (int ks = 0; ks < 4; ks++) {
            // transpose P fragments C-layout -> A-layout via quad shuffles
            float e0 = __shfl_sync(0xffffffff, sacc[ks][0], srcA);
            float o0 = __shfl_sync(0xffffffff, sacc[ks][1], srcA);
            float e1 = __shfl_sync(0xffffffff, sacc[ks][2], srcA);
            float o1 = __shfl_sync(0xffffffff, sacc[ks][3], srcA);
            float e2 = __shfl_sync(0xffffffff, sacc[ks][0], srcB);
            float o2 = __shfl_sync(0xffffffff, sacc[ks][1], srcB);
            float e3 = __shfl_sync(0xffffffff, sacc[ks][2], srcB);
            float o3 = __shfl_sync(0xffffffff, sacc[ks][3], srcB);
            uint32_t a0 = fbits(odd ? o0 : e0);   // P[g   ][8ks+tig]
            uint32_t a1 = fbits(odd ? o1 : e1);   // P[g+8 ][8ks+tig]
            uint32_t a2 = fbits(odd ? o2 : e2);   // P[g   ][8ks+tig+4]
            uint32_t a3 = fbits(odd ? o3 : e3);   // P[g+8 ][8ks+tig+4]

            const int vr0 = kvh + ks * 8 + tig;
            const int vr1 = vr0 + 4;
#pragma unroll
            for (int dt = 0; dt < 16; dt++) {
                uint32_t b0 = fbits(Vs[vr0 * 136 + dt * 8 + g]);
                uint32_t b1 = fbits(Vs[vr1 * 136 + dt * 8 + g]);
                mma_tf32(oacc[dt][0], oacc[dt][1], oacc[dt][2], oacc[dt][3],
                         a0, a1, a2, a3, b0, b1);
            }
        }
    }

    // ---- split-kv merge (half1 -> smem, half0 combines & writes) ----
    __syncthreads();
    float* Os = sm + MG_O;
    float* ML = sm + MG_ML;
    if (half == 1) {
#pragma unroll
        for (int dt = 0; dt < 16; dt++) {
            int col = dt * 8 + tig * 2;
            Os[(r0 + g) * 128 + col]         = oacc[dt][0];
            Os[(r0 + g) * 128 + col + 1]     = oacc[dt][1];
            Os[(r0 + g + 8) * 128 + col]     = oacc[dt][2];
            Os[(r0 + g + 8) * 128 + col + 1] = oacc[dt][3];
        }
        if (tig == 0) {
            ML[(r0 + g) * 2]     = m0r;  ML[(r0 + g) * 2 + 1]     = l0r;
            ML[(r0 + g + 8) * 2] = m1r;  ML[(r0 + g + 8) * 2 + 1] = l1r;
        }
    }
    __syncthreads();
    if (half == 0) {
        float mb0 = ML[(r0 + g) * 2],     lb0 = ML[(r0 + g) * 2 + 1];
        float mb1 = ML[(r0 + g + 8) * 2], lb1 = ML[(r0 + g + 8) * 2 + 1];
        float ms0 = fmaxf(m0r, mb0);
        float w00 = __expf(m0r - ms0), w01 = __expf(mb0 - ms0);
        float rl0 = 1.0f / (l0r * w00 + lb0 * w01);
        float ms1 = fmaxf(m1r, mb1);
        float w10 = __expf(m1r - ms1), w11 = __expf(mb1 - ms1);
        float rl1 = 1.0f / (l1r * w10 + lb1 * w11);
#pragma unroll
        for (int dt = 0; dt < 16; dt++) {
            int col = dt * 8 + tig * 2;
            float2 u0, u1;
            u0.x = (oacc[dt][0] * w00 + Os[(r0 + g) * 128 + col]     * w01) * rl0;
            u0.y = (oacc[dt][1] * w00 + Os[(r0 + g) * 128 + col + 1] * w01) * rl0;
            u1.x = (oacc[dt][2] * w10 + Os[(r0 + g + 8) * 128 + col]     * w11) * rl1;
            u1.y = (oacc[dt][3] * w10 + Os[(r0 + g + 8) * 128 + col + 1] * w11) * rl1;
            *(float2*)&out[(size_t)(b * LQ + q0 + r0 + g) * DKD + col]     = u0;
            *(float2*)&out[(size_t)(b * LQ + q0 + r0 + g + 8) * DKD + col] = u1;
        }
    }
}

// ---------------------------------------------------------------------------
extern "C" void kernel_launch(void* const* d_in, const int* in_sizes, int n_in,
                              void* d_out, int out_size)
{
    const float* q  = (const float*)d_in[0];
    const float* k  = (const float*)d_in[1];
    const float* v  = (const float*)d_in[2];
    const int* mlen = (const int*)d_in[3];
    const float* Wq = (const float*)d_in[4];
    const float* Wk = (const float*)d_in[5];
    const float* Wv = (const float*)d_in[6];
    float* out = (float*)d_out;

    cudaFuncSetAttribute(proj_mma, cudaFuncAttributeMaxDynamicSharedMemorySize, PJ_SMB);
    dim3 pgrid(BB * LQ / 128, 1, 3);
    proj_mma<<<pgrid, 256, PJ_SMB>>>(q, k, v, Wq, Wk, Wv);

    cudaFuncSetAttribute(attn_mma, cudaFuncAttributeMaxDynamicSharedMemorySize, AT_SMB);
    dim3 agrid(LQ / 128, BB);
    attn_mma<<<agrid, 512, AT_SMB>>>(mlen, out);
}

// round 7
// speedup vs baseline: 2.8827x; 2.8827x over previous
#include <cuda_runtime.h>
#include <cuda_fp16.h>
#include <cstdint>

// Problem constants
#define BB 8
#define LQ 2048
#define LK 2048
#define DW 1024
#define DKD 128
#define INV_TEMP 0.08838834764831845f   // 1/sqrt(128)

// Projected q/k/v scratch (fp16) + transposed fp16 weights
__device__ __half g_qs[BB * LQ * DKD];
__device__ __half g_ks[BB * LK * DKD];
__device__ __half g_vs[BB * LK * DKD];
__device__ __half g_wt[3 * DKD * DW];    // [z][n][k]

// ---------------------------------------------------------------------------
// helpers
// ---------------------------------------------------------------------------
__device__ __forceinline__ void ldsm4(uint32_t& r0, uint32_t& r1, uint32_t& r2,
                                      uint32_t& r3, uint32_t a) {
    asm volatile("ldmatrix.sync.aligned.m8n8.x4.shared.b16 {%0,%1,%2,%3}, [%4];"
                 : "=r"(r0), "=r"(r1), "=r"(r2), "=r"(r3) : "r"(a));
}
__device__ __forceinline__ void ldsm4t(uint32_t& r0, uint32_t& r1, uint32_t& r2,
                                       uint32_t& r3, uint32_t a) {
    asm volatile("ldmatrix.sync.aligned.m8n8.x4.trans.shared.b16 {%0,%1,%2,%3}, [%4];"
                 : "=r"(r0), "=r"(r1), "=r"(r2), "=r"(r3) : "r"(a));
}
// mma m16n8k16 fp16 in, fp32 accum
__device__ __forceinline__ void mma_f16(float* c, uint32_t a0, uint32_t a1,
                                        uint32_t a2, uint32_t a3,
                                        uint32_t b0, uint32_t b1) {
    asm volatile(
        "mma.sync.aligned.m16n8k16.row.col.f32.f16.f16.f32 "
        "{%0,%1,%2,%3}, {%4,%5,%6,%7}, {%8,%9}, {%0,%1,%2,%3};"
        : "+f"(c[0]), "+f"(c[1]), "+f"(c[2]), "+f"(c[3])
        : "r"(a0), "r"(a1), "r"(a2), "r"(a3), "r"(b0), "r"(b1));
}
__device__ __forceinline__ uint32_t su32(const void* p) {
    return (uint32_t)__cvta_generic_to_shared(p);
}

// ---------------------------------------------------------------------------
// Weight prep: g_wt[z][n][k] = fp16(W_z[k][n])
// ---------------------------------------------------------------------------
__global__ __launch_bounds__(256) void prep_wt(
    const float* __restrict__ Wq, const float* __restrict__ Wk,
    const float* __restrict__ Wv)
{
    __shared__ float t[32][33];
    const float* W = blockIdx.z == 0 ? Wq : blockIdx.z == 1 ? Wk : Wv;
    __half* Wt = g_wt + (size_t)blockIdx.z * DKD * DW;
    const int k0 = blockIdx.x * 32, n0 = blockIdx.y * 32;
    const int c = threadIdx.x & 31, r8 = threadIdx.x >> 5;
#pragma unroll
    for (int rr = r8; rr < 32; rr += 8)
        t[rr][c] = W[(size_t)(k0 + rr) * DKD + n0 + c];
    __syncthreads();
#pragma unroll
    for (int rr = r8; rr < 32; rr += 8)
        Wt[(size_t)(n0 + rr) * DW + k0 + c] = __float2half_rn(t[c][rr]);
}

// ---------------------------------------------------------------------------
// Projection GEMM, fp16 mma + ldmatrix, register-prefetch double buffering.
// C[16384,128] = A[16384,1024] x W[1024,128], per-CTA 128x128 tile, BK=32.
// 256 threads = 8 warps, warp tile 32(M) x 64(N).
// K/V CTAs whose rows lie past ceil64(memlen) exit early (never read).
// ---------------------------------------------------------------------------
__global__ __launch_bounds__(256) void proj_f16(
    const float* __restrict__ q, const float* __restrict__ k,
    const float* __restrict__ v, const int* __restrict__ memory_lengths)
{
    __shared__ __half As[2][128 * 40];
    __shared__ __half Ws[2][128 * 40];

    const int z = blockIdx.z;
    const int row0 = blockIdx.x * 128;
    if (z > 0) {
        const int ml = memory_lengths[row0 >> 11];
        if ((row0 & 2047) >= ((ml + 63) & ~63)) return;
    }

    const float* A = z == 0 ? q : z == 1 ? k : v;
    const __half* Wt = g_wt + (size_t)z * DKD * DW;
    __half* C = z == 0 ? g_qs : z == 1 ? g_ks : g_vs;

    const int tid  = threadIdx.x;
    const int lane = tid & 31;
    const int warp = tid >> 5;
    const int g    = lane >> 2;
    const int tig  = lane & 3;
    const int m0   = (warp & 3) * 32;
    const int n0   = (warp >> 2) * 64;

    float acc[2][8][4];
#pragma unroll
    for (int mt = 0; mt < 2; mt++)
#pragma unroll
        for (int nt = 0; nt < 8; nt++)
#pragma unroll
            for (int c = 0; c < 4; c++) acc[mt][nt][c] = 0.0f;

    float4 apre[4];
    uint4  wpre[2];
    auto prefetch = [&](int k0c) {
#pragma unroll
        for (int it = 0; it < 4; it++) {
            int f4 = tid + it * 256;
            int r = f4 >> 3, c4 = f4 & 7;
            apre[it] = *(const float4*)&A[(size_t)(row0 + r) * DW + k0c + c4 * 4];
        }
#pragma unroll
        for (int it = 0; it < 2; it++) {
            int f8 = tid + it * 256;
            int r = f8 >> 2, c8 = f8 & 3;
            wpre[it] = *(const uint4*)&Wt[(size_t)r * DW + k0c + c8 * 8];
        }
    };
    auto store_tiles = [&](int buf) {
#pragma unroll
        for (int it = 0; it < 4; it++) {
            int f4 = tid + it * 256;
            int r = f4 >> 3, c4 = f4 & 7;
            __half2* d = (__half2*)&As[buf][r * 40 + c4 * 4];
            d[0] = __floats2half2_rn(apre[it].x, apre[it].y);
            d[1] = __floats2half2_rn(apre[it].z, apre[it].w);
        }
#pragma unroll
        for (int it = 0; it < 2; it++) {
            int f8 = tid + it * 256;
            int r = f8 >> 2, c8 = f8 & 3;
            *(uint4*)&Ws[buf][r * 40 + c8 * 8] = wpre[it];
        }
    };

    // ldmatrix lane addressing (within a buffer)
    const uint32_t a_row = (uint32_t)(m0 + (lane & 15));
    const uint32_t a_kof = (uint32_t)((lane >> 4) * 8);
    const uint32_t b_row = (uint32_t)((lane & 7) + ((lane >> 4) << 3));
    const uint32_t b_kof = (uint32_t)(((lane >> 3) & 1) * 8);

    prefetch(0);

    for (int i = 0; i < 32; i++) {
        const int buf = i & 1;
        __syncthreads();
        store_tiles(buf);
        if (i + 1 < 32) prefetch((i + 1) * 32);
        __syncthreads();

        const uint32_t sa = su32(&As[buf][0]);
        const uint32_t sw = su32(&Ws[buf][0]);

#pragma unroll
        for (int kk = 0; kk < 32; kk += 16) {
            uint32_t a[2][4];
#pragma unroll
            for (int mt = 0; mt < 2; mt++)
                ldsm4(a[mt][0], a[mt][1], a[mt][2], a[mt][3],
                      sa + ((a_row + mt * 16) * 40 + a_kof + kk) * 2);
#pragma unroll
            for (int nt = 0; nt < 4; nt++) {
                uint32_t b0, b1, b2, b3;
                ldsm4(b0, b1, b2, b3,
                      sw + ((n0 + nt * 16 + b_row) * 40 + b_kof + kk) * 2);
#pragma unroll
                for (int mt = 0; mt < 2; mt++) {
                    mma_f16(acc[mt][nt * 2],     a[mt][0], a[mt][1], a[mt][2], a[mt][3], b0, b1);
                    mma_f16(acc[mt][nt * 2 + 1], a[mt][0], a[mt][1], a[mt][2], a[mt][3], b2, b3);
                }
            }
        }
    }

    // Epilogue: fp16 outputs
#pragma unroll
    for (int mt = 0; mt < 2; mt++) {
        int r0 = row0 + m0 + mt * 16 + g;
#pragma unroll
        for (int nt = 0; nt < 8; nt++) {
            int col = n0 + nt * 8 + tig * 2;
            *(__half2*)&C[(size_t)r0 * DKD + col] =
                __floats2half2_rn(acc[mt][nt][0], acc[mt][nt][1]);
            *(__half2*)&C[(size_t)(r0 + 8) * DKD + col] =
                __floats2half2_rn(acc[mt][nt][2], acc[mt][nt][3]);
        }
    }
}

// ---------------------------------------------------------------------------
// Fused flash attention, fp16 mma + ldmatrix. 64 q-rows/CTA, K-blocks of 64,
// 512 threads = 16 warps. S warp tile 16x16 (4 q-groups x 4 kv-groups);
// PV warp tile 16x32 (4 q-groups x 4 d-groups). Register-prefetched K/V.
// smem halves: Q 64x136, K 64x136, V 64x136, P 64x72; fp32: S 64x68 + stats.
// ---------------------------------------------------------------------------
#define QH_OFF 0
#define KH_OFF (64 * 136)                 // 8704
#define VH_OFF (2 * 64 * 136)             // 17408
#define PH_OFF (3 * 64 * 136)             // 26112
#define H_TOT  (PH_OFF + 64 * 72)         // 30720 halves
#define SS_BYT (H_TOT * 2)                // 61440
#define SS_ST  68
#define AT_SMB (SS_BYT + 64 * SS_ST * 4 + 192 * 4)   // 79616

__global__ __launch_bounds__(512) void attn_f16(
    const int* __restrict__ memory_lengths, float* __restrict__ out)
{
    extern __shared__ char smc[];
    __half* Qs = (__half*)smc + QH_OFF;
    __half* Ks = (__half*)smc + KH_OFF;
    __half* Vs = (__half*)smc + VH_OFF;
    __half* Ps = (__half*)smc + PH_OFF;
    float* Ss  = (float*)(smc + SS_BYT);
    float* m_s  = Ss + 64 * SS_ST;
    float* l_s  = m_s + 64;
    float* sc_s = l_s + 64;

    const int tid  = threadIdx.x;
    const int lane = tid & 31;
    const int warp = tid >> 5;
    const int g    = lane >> 2;
    const int tig  = lane & 3;
    const int b    = blockIdx.y;
    const int q0   = blockIdx.x * 64;
    const int memlen = memory_lengths[b];

    const int sm0 = (warp & 3) * 16;    // q rows
    const int sn0 = (warp >> 2) * 16;   // kv cols (S phase)
    const int pn0 = (warp >> 2) * 32;   // d cols (PV phase)

    const __half* Q = g_qs + (size_t)b * LQ * DKD;
    const __half* K = g_ks + (size_t)b * LK * DKD;
    const __half* V = g_vs + (size_t)b * LK * DKD;

    // Load Q tile 64x128 halves = 1024 uint4
#pragma unroll
    for (int it = 0; it < 2; it++) {
        int f8 = tid + it * 512;
        int r = f8 >> 4, c8 = f8 & 15;
        *(uint4*)(Qs + r * 136 + c8 * 8) =
            *(const uint4*)&Q[(size_t)(q0 + r) * DKD + c8 * 8];
    }
    if (tid < 64) { m_s[tid] = -1e30f; l_s[tid] = 0.0f; }

    float oacc[4][4];
#pragma unroll
    for (int nt = 0; nt < 4; nt++)
#pragma unroll
        for (int c = 0; c < 4; c++) oacc[nt][c] = 0.0f;

    const int nkb = (memlen + 63) >> 6;

    uint4 kpre[2], vpre[2];
#pragma unroll
    for (int it = 0; it < 2; it++) {
        int f8 = tid + it * 512;
        int r = f8 >> 4, c8 = f8 & 15;
        kpre[it] = *(const uint4*)&K[(size_t)r * DKD + c8 * 8];
        vpre[it] = *(const uint4*)&V[(size_t)r * DKD + c8 * 8];
    }

    // ldmatrix lane bases (halves)
    const uint32_t sbase = su32(smc);
    const uint32_t qa = sbase + ((QH_OFF + (sm0 + (lane & 15)) * 136 + (lane >> 4) * 8)) * 2;
    const uint32_t kb_ = sbase + ((KH_OFF + (sn0 + (lane & 7) + ((lane >> 4) << 3)) * 136
                                   + ((lane >> 3) & 1) * 8)) * 2;
    const uint32_t pa = sbase + ((PH_OFF + (sm0 + (lane & 15)) * 72 + (lane >> 4) * 8)) * 2;
    const uint32_t vb = sbase + ((VH_OFF + ((lane & 7) + ((lane >> 3) & 1) * 8) * 136
                                   + pn0 + (lane >> 4) * 8)) * 2;

    for (int kb = 0; kb < nkb; kb++) {
        const int kv0 = kb * 64;
        __syncthreads();
#pragma unroll
        for (int it = 0; it < 2; it++) {
            int f8 = tid + it * 512;
            int r = f8 >> 4, c8 = f8 & 15;
            *(uint4*)(Ks + r * 136 + c8 * 8) = kpre[it];
            *(uint4*)(Vs + r * 136 + c8 * 8) = vpre[it];
        }
        if (kb + 1 < nkb) {
            const int nv0 = kv0 + 64;
#pragma unroll
            for (int it = 0; it < 2; it++) {
                int f8 = tid + it * 512;
                int r = f8 >> 4, c8 = f8 & 15;
                kpre[it] = *(const uint4*)&K[(size_t)(nv0 + r) * DKD + c8 * 8];
                vpre[it] = *(const uint4*)&V[(size_t)(nv0 + r) * DKD + c8 * 8];
            }
        }
        __syncthreads();

        // ---- S = Q K^T (warp tile 16x16) ----
        float sacc[2][4];
#pragma unroll
        for (int nt = 0; nt < 2; nt++)
#pragma unroll
            for (int c = 0; c < 4; c++) sacc[nt][c] = 0.0f;

#pragma unroll
        for (int kk = 0; kk < 128; kk += 16) {
            uint32_t a0, a1, a2, a3, b0, b1, b2, b3;
            ldsm4(a0, a1, a2, a3, qa + kk * 2);
            ldsm4(b0, b1, b2, b3, kb_ + kk * 2);
            mma_f16(sacc[0], a0, a1, a2, a3, b0, b1);
            mma_f16(sacc[1], a0, a1, a2, a3, b2, b3);
        }
#pragma unroll
        for (int nt = 0; nt < 2; nt++) {
            int col = sn0 + nt * 8 + tig * 2;
            Ss[(sm0 + g) * SS_ST + col]         = sacc[nt][0];
            Ss[(sm0 + g) * SS_ST + col + 1]     = sacc[nt][1];
            Ss[(sm0 + g + 8) * SS_ST + col]     = sacc[nt][2];
            Ss[(sm0 + g + 8) * SS_ST + col + 1] = sacc[nt][3];
        }
        __syncthreads();

        // ---- online softmax: 8 threads/row, P -> fp16 buffer ----
        {
            const int r  = tid >> 3;
            const int q8 = tid & 7;
            float m_old = m_s[r];
            float sv[8];
            float mx = m_old;
#pragma unroll
            for (int j = 0; j < 8; j++) {
                int c = q8 * 8 + j;
                float s = Ss[r * SS_ST + c] * INV_TEMP;
                if (kv0 + c >= memlen) s = -1e30f;
                sv[j] = s;
                mx = fmaxf(mx, s);
            }
            mx = fmaxf(mx, __shfl_xor_sync(0xffffffff, mx, 1));
            mx = fmaxf(mx, __shfl_xor_sync(0xffffffff, mx, 2));
            mx = fmaxf(mx, __shfl_xor_sync(0xffffffff, mx, 4));
            float sum = 0.0f;
#pragma unroll
            for (int j = 0; j < 8; j += 2) {
                float p0 = __expf(sv[j] - mx);
                float p1 = __expf(sv[j + 1] - mx);
                sum += p0 + p1;
                *(__half2*)(Ps + r * 72 + q8 * 8 + j) = __floats2half2_rn(p0, p1);
            }
            sum += __shfl_xor_sync(0xffffffff, sum, 1);
            sum += __shfl_xor_sync(0xffffffff, sum, 2);
            sum += __shfl_xor_sync(0xffffffff, sum, 4);
            float scale = __expf(m_old - mx);
            if (q8 == 0) {
                m_s[r] = mx;
                l_s[r] = l_s[r] * scale + sum;
                sc_s[r] = scale;
            }
        }
        __syncthreads();

        // ---- O = O*scale + P @ V (warp tile 16x32) ----
        float sc0 = sc_s[sm0 + g];
        float sc1 = sc_s[sm0 + g + 8];
#pragma unroll
        for (int nt = 0; nt < 4; nt++) {
            oacc[nt][0] *= sc0; oacc[nt][1] *= sc0;
            oacc[nt][2] *= sc1; oacc[nt][3] *= sc1;
        }
#pragma unroll
        for (int kc = 0; kc < 4; kc++) {
            uint32_t p0, p1, p2, p3, v0, v1, v2, v3, w0, w1, w2, w3;
            ldsm4(p0, p1, p2, p3, pa + kc * 16 * 2);
            ldsm4t(v0, v1, v2, v3, vb + kc * 16 * 136 * 2);
            ldsm4t(w0, w1, w2, w3, vb + kc * 16 * 136 * 2 + 16 * 2);
            mma_f16(oacc[0], p0, p1, p2, p3, v0, v1);
            mma_f16(oacc[1], p0, p1, p2, p3, v2, v3);
            mma_f16(oacc[2], p0, p1, p2, p3, w0, w1);
            mma_f16(oacc[3], p0, p1, p2, p3, w2, w3);
        }
    }

    // ---- normalize & write out (fp32) ----
    float rl0 = 1.0f / l_s[sm0 + g];
    float rl1 = 1.0f / l_s[sm0 + g + 8];
#pragma unroll
    for (int nt = 0; nt < 4; nt++) {
        int col = pn0 + nt * 8 + tig * 2;
        int r0 = q0 + sm0 + g;
        float2 o0 = make_float2(oacc[nt][0] * rl0, oacc[nt][1] * rl0);
        float2 o1 = make_float2(oacc[nt][2] * rl1, oacc[nt][3] * rl1);
        *(float2*)&out[(size_t)(b * LQ + r0) * DKD + col]     = o0;
        *(float2*)&out[(size_t)(b * LQ + r0 + 8) * DKD + col] = o1;
    }
}

// ---------------------------------------------------------------------------
extern "C" void kernel_launch(void* const* d_in, const int* in_sizes, int n_in,
                              void* d_out, int out_size)
{
    const float* q  = (const float*)d_in[0];
    const float* k  = (const float*)d_in[1];
    const float* v  = (const float*)d_in[2];
    const int* mlen = (const int*)d_in[3];
    const float* Wq = (const float*)d_in[4];
    const float* Wk = (const float*)d_in[5];
    const float* Wv = (const float*)d_in[6];
    float* out = (float*)d_out;

    // Phase 0: transpose + round weights to fp16 (tiny)
    dim3 wgrid(DW / 32, DKD / 32, 3);
    prep_wt<<<wgrid, 256>>>(Wq, Wk, Wv);

    // Phase 1: fp16 projections with K/V early exit
    dim3 pgrid(BB * LQ / 128, 1, 3);
    proj_f16<<<pgrid, 256>>>(q, k, v, mlen);

    // Phase 2: fused masked attention (fp16 mma + ldmatrix)
    cudaFuncSetAttribute(attn_f16, cudaFuncAttributeMaxDynamicSharedMemorySize, AT_SMB);
    dim3 agrid(LQ / 64, BB);
    attn_f16<<<agrid, 512, AT_SMB>>>(mlen, out);
}

// round 11
// speedup vs baseline: 3.0201x; 1.0477x over previous
#include <cuda_runtime.h>
#include <cuda_fp16.h>
#include <cstdint>

// Problem constants
#define BB 8
#define LQ 2048
#define LK 2048
#define DW 1024
#define DKD 128
#define INV_TEMP 0.08838834764831845f   // 1/sqrt(128)

// Projected q/k/v scratch (fp16) + transposed fp16 weights
__device__ __half g_qs[BB * LQ * DKD];
__device__ __half g_ks[BB * LK * DKD];
__device__ __half g_vs[BB * LK * DKD];
__device__ __half g_wt[3 * DKD * DW];    // [z][n][k]

// ---------------------------------------------------------------------------
// helpers
// ---------------------------------------------------------------------------
__device__ __forceinline__ void ldsm4(uint32_t& r0, uint32_t& r1, uint32_t& r2,
                                      uint32_t& r3, uint32_t a) {
    asm volatile("ldmatrix.sync.aligned.m8n8.x4.shared.b16 {%0,%1,%2,%3}, [%4];"
                 : "=r"(r0), "=r"(r1), "=r"(r2), "=r"(r3) : "r"(a));
}
__device__ __forceinline__ void ldsm4t(uint32_t& r0, uint32_t& r1, uint32_t& r2,
                                       uint32_t& r3, uint32_t a) {
    asm volatile("ldmatrix.sync.aligned.m8n8.x4.trans.shared.b16 {%0,%1,%2,%3}, [%4];"
                 : "=r"(r0), "=r"(r1), "=r"(r2), "=r"(r3) : "r"(a));
}
// mma m16n8k16 fp16 in, fp32 accum
__device__ __forceinline__ void mma_f16(float* c, uint32_t a0, uint32_t a1,
                                        uint32_t a2, uint32_t a3,
                                        uint32_t b0, uint32_t b1) {
    asm volatile(
        "mma.sync.aligned.m16n8k16.row.col.f32.f16.f16.f32 "
        "{%0,%1,%2,%3}, {%4,%5,%6,%7}, {%8,%9}, {%0,%1,%2,%3};"
        : "+f"(c[0]), "+f"(c[1]), "+f"(c[2]), "+f"(c[3])
        : "r"(a0), "r"(a1), "r"(a2), "r"(a3), "r"(b0), "r"(b1));
}
__device__ __forceinline__ uint32_t su32(const void* p) {
    return (uint32_t)__cvta_generic_to_shared(p);
}
__device__ __forceinline__ void cp16(uint32_t saddr, const void* gaddr) {
    asm volatile("cp.async.cg.shared.global [%0], [%1], 16;" :: "r"(saddr), "l"(gaddr));
}

// ---------------------------------------------------------------------------
// Weight prep: g_wt[z][n][k] = fp16(W_z[k][n])
// ---------------------------------------------------------------------------
__global__ __launch_bounds__(256) void prep_wt(
    const float* __restrict__ Wq, const float* __restrict__ Wk,
    const float* __restrict__ Wv)
{
    __shared__ float t[32][33];
    const float* W = blockIdx.z == 0 ? Wq : blockIdx.z == 1 ? Wk : Wv;
    __half* Wt = g_wt + (size_t)blockIdx.z * DKD * DW;
    const int k0 = blockIdx.x * 32, n0 = blockIdx.y * 32;
    const int c = threadIdx.x & 31, r8 = threadIdx.x >> 5;
#pragma unroll
    for (int rr = r8; rr < 32; rr += 8)
        t[rr][c] = W[(size_t)(k0 + rr) * DKD + n0 + c];
    __syncthreads();
#pragma unroll
    for (int rr = r8; rr < 32; rr += 8)
        Wt[(size_t)(n0 + rr) * DW + k0 + c] = __float2half_rn(t[c][rr]);
}

// ---------------------------------------------------------------------------
// Projection GEMM, fp16 mma + ldmatrix, register-prefetch double buffering.
// (unchanged from the proven R6 version)
// ---------------------------------------------------------------------------
__global__ __launch_bounds__(256) void proj_f16(
    const float* __restrict__ q, const float* __restrict__ k,
    const float* __restrict__ v, const int* __restrict__ memory_lengths)
{
    __shared__ __half As[2][128 * 40];
    __shared__ __half Ws[2][128 * 40];

    const int z = blockIdx.z;
    const int row0 = blockIdx.x * 128;
    if (z > 0) {
        const int ml = memory_lengths[row0 >> 11];
        if ((row0 & 2047) >= ((ml + 63) & ~63)) return;
    }

    const float* A = z == 0 ? q : z == 1 ? k : v;
    const __half* Wt = g_wt + (size_t)z * DKD * DW;
    __half* C = z == 0 ? g_qs : z == 1 ? g_ks : g_vs;

    const int tid  = threadIdx.x;
    const int lane = tid & 31;
    const int warp = tid >> 5;
    const int g    = lane >> 2;
    const int tig  = lane & 3;
    const int m0   = (warp & 3) * 32;
    const int n0   = (warp >> 2) * 64;

    float acc[2][8][4];
#pragma unroll
    for (int mt = 0; mt < 2; mt++)
#pragma unroll
        for (int nt = 0; nt < 8; nt++)
#pragma unroll
            for (int c = 0; c < 4; c++) acc[mt][nt][c] = 0.0f;

    float4 apre[4];
    uint4  wpre[2];
    auto prefetch = [&](int k0c) {
#pragma unroll
        for (int it = 0; it < 4; it++) {
            int f4 = tid + it * 256;
            int r = f4 >> 3, c4 = f4 & 7;
            apre[it] = *(const float4*)&A[(size_t)(row0 + r) * DW + k0c + c4 * 4];
        }
#pragma unroll
        for (int it = 0; it < 2; it++) {
            int f8 = tid + it * 256;
            int r = f8 >> 2, c8 = f8 & 3;
            wpre[it] = *(const uint4*)&Wt[(size_t)r * DW + k0c + c8 * 8];
        }
    };
    auto store_tiles = [&](int buf) {
#pragma unroll
        for (int it = 0; it < 4; it++) {
            int f4 = tid + it * 256;
            int r = f4 >> 3, c4 = f4 & 7;
            __half2* d = (__half2*)&As[buf][r * 40 + c4 * 4];
            d[0] = __floats2half2_rn(apre[it].x, apre[it].y);
            d[1] = __floats2half2_rn(apre[it].z, apre[it].w);
        }
#pragma unroll
        for (int it = 0; it < 2; it++) {
            int f8 = tid + it * 256;
            int r = f8 >> 2, c8 = f8 & 3;
            *(uint4*)&Ws[buf][r * 40 + c8 * 8] = wpre[it];
        }
    };

    const uint32_t a_row = (uint32_t)(m0 + (lane & 15));
    const uint32_t a_kof = (uint32_t)((lane >> 4) * 8);
    const uint32_t b_row = (uint32_t)((lane & 7) + ((lane >> 4) << 3));
    const uint32_t b_kof = (uint32_t)(((lane >> 3) & 1) * 8);

    prefetch(0);

    for (int i = 0; i < 32; i++) {
        const int buf = i & 1;
        __syncthreads();
        store_tiles(buf);
        if (i + 1 < 32) prefetch((i + 1) * 32);
        __syncthreads();

        const uint32_t sa = su32(&As[buf][0]);
        const uint32_t sw = su32(&Ws[buf][0]);

#pragma unroll
        for (int kk = 0; kk < 32; kk += 16) {
            uint32_t a[2][4];
#pragma unroll
            for (int mt = 0; mt < 2; mt++)
                ldsm4(a[mt][0], a[mt][1], a[mt][2], a[mt][3],
                      sa + ((a_row + mt * 16) * 40 + a_kof + kk) * 2);
#pragma unroll
            for (int nt = 0; nt < 4; nt++) {
                uint32_t b0, b1, b2, b3;
                ldsm4(b0, b1, b2, b3,
                      sw + ((n0 + nt * 16 + b_row) * 40 + b_kof + kk) * 2);
#pragma unroll
                for (int mt = 0; mt < 2; mt++) {
                    mma_f16(acc[mt][nt * 2],     a[mt][0], a[mt][1], a[mt][2], a[mt][3], b0, b1);
                    mma_f16(acc[mt][nt * 2 + 1], a[mt][0], a[mt][1], a[mt][2], a[mt][3], b2, b3);
                }
            }
        }
    }

#pragma unroll
    for (int mt = 0; mt < 2; mt++) {
        int r0 = row0 + m0 + mt * 16 + g;
#pragma unroll
        for (int nt = 0; nt < 8; nt++) {
            int col = n0 + nt * 8 + tig * 2;
            *(__half2*)&C[(size_t)r0 * DKD + col] =
                __floats2half2_rn(acc[mt][nt][0], acc[mt][nt][1]);
            *(__half2*)&C[(size_t)(r0 + 8) * DKD + col] =
                __floats2half2_rn(acc[mt][nt][2], acc[mt][nt][3]);
        }
    }
}

// ---------------------------------------------------------------------------
// Fused flash attention, fp16 mma + ldmatrix + cp.async pipeline.
// 64 q-rows/CTA, K-blocks of 64, 512 threads = 16 warps, target 2 CTAs/SM.
// K single-buffered (refilled right after S-phase barrier), V double-buffered.
// 3 barriers per K-block; loads for kb+1 overlap softmax+PV of kb.
// ---------------------------------------------------------------------------
#define QH_OFF 0
#define KH_OFF (64 * 136)                 // 8704
#define V0_OFF (2 * 64 * 136)             // 17408
#define V1_OFF (3 * 64 * 136)             // 26112
#define PH_OFF (4 * 64 * 136)             // 34816
#define H_TOT  (PH_OFF + 64 * 72)         // 39424 halves
#define SS_BYT (H_TOT * 2)                // 78848
#define SS_ST  68
#define AT_SMB (SS_BYT + 64 * SS_ST * 4 + 192 * 4)   // 97024

__global__ __launch_bounds__(512, 2) void attn_f16(
    const int* __restrict__ memory_lengths, float* __restrict__ out)
{
    extern __shared__ char smc[];
    __half* Ps = (__half*)smc + PH_OFF;
    float* Ss  = (float*)(smc + SS_BYT);
    float* m_s  = Ss + 64 * SS_ST;
    float* l_s  = m_s + 64;
    float* sc_s = l_s + 64;

    const int tid  = threadIdx.x;
    const int lane = tid & 31;
    const int warp = tid >> 5;
    const int g    = lane >> 2;
    const int tig  = lane & 3;
    const int b    = blockIdx.y;
    const int q0   = blockIdx.x * 64;
    const int memlen = memory_lengths[b];

    const int sm0 = (warp & 3) * 16;    // q rows
    const int sn0 = (warp >> 2) * 16;   // kv cols (S phase)
    const int pn0 = (warp >> 2) * 32;   // d cols (PV phase)

    const __half* Q = g_qs + (size_t)b * LQ * DKD;
    const __half* K = g_ks + (size_t)b * LK * DKD;
    const __half* V = g_vs + (size_t)b * LK * DKD;

    const uint32_t sbase = su32(smc);
    // per-thread tile-copy mapping (64x128 halves = 1024 16B chunks, 2/thread)
    const int cr  = tid >> 4;           // row 0..31 (+32 on second it)
    const int cc8 = tid & 15;           // col group

    auto issue_q = [&]() {
#pragma unroll
        for (int it = 0; it < 2; it++) {
            int r = cr + it * 32;
            cp16(sbase + (uint32_t)(QH_OFF + r * 136 + cc8 * 8) * 2,
                 &Q[(size_t)(q0 + r) * DKD + cc8 * 8]);
        }
    };
    auto issue_k = [&](int kv0) {
#pragma unroll
        for (int it = 0; it < 2; it++) {
            int r = cr + it * 32;
            cp16(sbase + (uint32_t)(KH_OFF + r * 136 + cc8 * 8) * 2,
                 &K[(size_t)(kv0 + r) * DKD + cc8 * 8]);
        }
    };
    auto issue_v = [&](int kv0, int vbuf) {
        const uint32_t vof = vbuf ? V1_OFF : V0_OFF;
#pragma unroll
        for (int it = 0; it < 2; it++) {
            int r = cr + it * 32;
            cp16(sbase + (vof + (uint32_t)(r * 136 + cc8 * 8)) * 2,
                 &V[(size_t)(kv0 + r) * DKD + cc8 * 8]);
        }
    };

    issue_q();
    issue_k(0);
    issue_v(0, 0);
    asm volatile("cp.async.commit_group;");

    if (tid < 64) { m_s[tid] = -1e30f; l_s[tid] = 0.0f; }

    float oacc[4][4];
#pragma unroll
    for (int nt = 0; nt < 4; nt++)
#pragma unroll
        for (int c = 0; c < 4; c++) oacc[nt][c] = 0.0f;

    const int nkb = (memlen + 63) >> 6;

    // ldmatrix lane bases (bytes)
    const uint32_t qa = sbase + (uint32_t)((QH_OFF + (sm0 + (lane & 15)) * 136
                                            + (lane >> 4) * 8)) * 2;
    const uint32_t ka = sbase + (uint32_t)((KH_OFF + (sn0 + (lane & 7) + ((lane >> 4) << 3)) * 136
                                            + ((lane >> 3) & 1) * 8)) * 2;
    const uint32_t pa = sbase + (uint32_t)((PH_OFF + (sm0 + (lane & 15)) * 72
                                            + (lane >> 4) * 8)) * 2;
    const uint32_t v_lane = (uint32_t)(((lane & 7) + ((lane >> 3) & 1) * 8) * 136
                                       + pn0 + (lane >> 4) * 8);
    const uint32_t vb0 = sbase + (uint32_t)(V0_OFF + v_lane) * 2;
    const uint32_t vb1 = sbase + (uint32_t)(V1_OFF + v_lane) * 2;

    for (int kb = 0; kb < nkb; kb++) {
        const int kv0 = kb * 64;
        asm volatile("cp.async.wait_group 0;");
        __syncthreads();                      // K/V(kb) + (kb==0: Q) visible

        // ---- S = Q K^T (warp tile 16x16) ----
        float sacc[2][4];
#pragma unroll
        for (int nt = 0; nt < 2; nt++)
#pragma unroll
            for (int c = 0; c < 4; c++) sacc[nt][c] = 0.0f;

#pragma unroll
        for (int kk = 0; kk < 128; kk += 16) {
            uint32_t a0, a1, a2, a3, b0, b1, b2, b3;
            ldsm4(a0, a1, a2, a3, qa + kk * 2);
            ldsm4(b0, b1, b2, b3, ka + kk * 2);
            mma_f16(sacc[0], a0, a1, a2, a3, b0, b1);
            mma_f16(sacc[1], a0, a1, a2, a3, b2, b3);
        }
#pragma unroll
        for (int nt = 0; nt < 2; nt++) {
            int col = sn0 + nt * 8 + tig * 2;
            Ss[(sm0 + g) * SS_ST + col]         = sacc[nt][0];
            Ss[(sm0 + g) * SS_ST + col + 1]     = sacc[nt][1];
            Ss[(sm0 + g + 8) * SS_ST + col]     = sacc[nt][2];
            Ss[(sm0 + g + 8) * SS_ST + col + 1] = sacc[nt][3];
        }
        __syncthreads();                      // S ready; K free

        // Kick off next block's K/V (overlaps softmax + PV)
        if (kb + 1 < nkb) {
            issue_k(kv0 + 64);
            issue_v(kv0 + 64, (kb + 1) & 1);
            asm volatile("cp.async.commit_group;");
        }

        // ---- online softmax: 8 threads/row, P -> fp16 buffer ----
        {
            const int r  = tid >> 3;
            const int q8 = tid & 7;
            float m_old = m_s[r];
            float sv[8];
            float mx = m_old;
#pragma unroll
            for (int j = 0; j < 8; j++) {
                int c = q8 * 8 + j;
                float s = Ss[r * SS_ST + c] * INV_TEMP;
                if (kv0 + c >= memlen) s = -1e30f;
                sv[j] = s;
                mx = fmaxf(mx, s);
            }
            mx = fmaxf(mx, __shfl_xor_sync(0xffffffff, mx, 1));
            mx = fmaxf(mx, __shfl_xor_sync(0xffffffff, mx, 2));
            mx = fmaxf(mx, __shfl_xor_sync(0xffffffff, mx, 4));
            float sum = 0.0f;
#pragma unroll
            for (int j = 0; j < 8; j += 2) {
                float p0 = __expf(sv[j] - mx);
                float p1 = __expf(sv[j + 1] - mx);
                sum += p0 + p1;
                *(__half2*)(Ps + r * 72 + q8 * 8 + j) = __floats2half2_rn(p0, p1);
            }
            sum += __shfl_xor_sync(0xffffffff, sum, 1);
            sum += __shfl_xor_sync(0xffffffff, sum, 2);
            sum += __shfl_xor_sync(0xffffffff, sum, 4);
            float scale = __expf(m_old - mx);
            if (q8 == 0) {
                m_s[r] = mx;
                l_s[r] = l_s[r] * scale + sum;
                sc_s[r] = scale;
            }
        }
        __syncthreads();                      // P + stats ready

        // ---- O = O*scale + P @ V (warp tile 16x32) ----
        float sc0 = sc_s[sm0 + g];
        float sc1 = sc_s[sm0 + g + 8];
#pragma unroll
        for (int nt = 0; nt < 4; nt++) {
            oacc[nt][0] *= sc0; oacc[nt][1] *= sc0;
            oacc[nt][2] *= sc1; oacc[nt][3] *= sc1;
        }
        const uint32_t vb = (kb & 1) ? vb1 : vb0;
#pragma unroll
        for (int kc = 0; kc < 4; kc++) {
            uint32_t p0, p1, p2, p3, v0, v1, v2, v3, w0, w1, w2, w3;
            ldsm4(p0, p1, p2, p3, pa + kc * 16 * 2);
            ldsm4t(v0, v1, v2, v3, vb + kc * 16 * 136 * 2);
            ldsm4t(w0, w1, w2, w3, vb + kc * 16 * 136 * 2 + 16 * 2);
            mma_f16(oacc[0], p0, p1, p2, p3, v0, v1);
            mma_f16(oacc[1], p0, p1, p2, p3, v2, v3);
            mma_f16(oacc[2], p0, p1, p2, p3, w0, w1);
            mma_f16(oacc[3], p0, p1, p2, p3, w2, w3);
        }
    }

    // ---- normalize & write out (fp32) ----
    float rl0 = 1.0f / l_s[sm0 + g];
    float rl1 = 1.0f / l_s[sm0 + g + 8];
#pragma unroll
    for (int nt = 0; nt < 4; nt++) {
        int col = pn0 + nt * 8 + tig * 2;
        int r0 = q0 + sm0 + g;
        float2 o0 = make_float2(oacc[nt][0] * rl0, oacc[nt][1] * rl0);
        float2 o1 = make_float2(oacc[nt][2] * rl1, oacc[nt][3] * rl1);
        *(float2*)&out[(size_t)(b * LQ + r0) * DKD + col]     = o0;
        *(float2*)&out[(size_t)(b * LQ + r0 + 8) * DKD + col] = o1;
    }
}

// ---------------------------------------------------------------------------
extern "C" void kernel_launch(void* const* d_in, const int* in_sizes, int n_in,
                              void* d_out, int out_size)
{
    const float* q  = (const float*)d_in[0];
    const float* k  = (const float*)d_in[1];
    const float* v  = (const float*)d_in[2];
    const int* mlen = (const int*)d_in[3];
    const float* Wq = (const float*)d_in[4];
    const float* Wk = (const float*)d_in[5];
    const float* Wv = (const float*)d_in[6];
    float* out = (float*)d_out;

    // Phase 0: transpose + round weights to fp16
    dim3 wgrid(DW / 32, DKD / 32, 3);
    prep_wt<<<wgrid, 256>>>(Wq, Wk, Wv);

    // Phase 1: fp16 projections with K/V early exit
    dim3 pgrid(BB * LQ / 128, 1, 3);
    proj_f16<<<pgrid, 256>>>(q, k, v, mlen);

    // Phase 2: fused masked attention (cp.async pipelined, 2 CTAs/SM)
    cudaFuncSetAttribute(attn_f16, cudaFuncAttributeMaxDynamicSharedMemorySize, AT_SMB);
    dim3 agrid(LQ / 64, BB);
    attn_f16<<<agrid, 512, AT_SMB>>>(mlen, out);
}